// round 1
// baseline (speedup 1.0000x reference)
#include <cuda_runtime.h>
#include <math.h>

// ---------------------------------------------------------------------------
// Problem constants
// ---------------------------------------------------------------------------
#define NROWS 8192       // 4B rows in rep
#define HALF  4096       // 2B rows per input
#define D     512        // embedding dim
#define BPOS  2048       // B (positive-pair offset unit)

// GEMM tiling
#define BM 128
#define BN 128
#define BK 16
#define TM 8
#define TN 8
#define NTHREADS 256

// ---------------------------------------------------------------------------
// Scratch (static device globals — no runtime allocation)
// ---------------------------------------------------------------------------
__device__ __align__(16) float g_rep[(size_t)NROWS * D];   // 16 MB normalized rows
__device__ double g_acc[2];                                 // [0]=S_offdiag, [1]=nominator

// ---------------------------------------------------------------------------
// FMA-only exp for x in ~[-2.5, 2.5] (avoids MUFU pipe entirely).
// exp(x) = 2^(x*log2e); round-to-nearest via magic constant, degree-5 poly
// for 2^r on r in [-0.5, 0.5]. Rel err <= ~4e-6.
// ---------------------------------------------------------------------------
__device__ __forceinline__ float fast_exp(float x) {
    float t  = x * 1.44269504088896341f;
    float fn = t + 12582912.0f;                 // 1.5 * 2^23, RN rounding
    int   m  = __float_as_int(fn) - 0x4B400000; // integer part of t
    float r  = t - (fn - 12582912.0f);          // fractional part in [-0.5, 0.5]
    float p  = 1.3333558146e-3f;
    p = fmaf(p, r, 9.6181291e-3f);
    p = fmaf(p, r, 5.5504108664e-2f);
    p = fmaf(p, r, 2.4022650696e-1f);
    p = fmaf(p, r, 6.9314718056e-1f);
    p = fmaf(p, r, 1.0f);
    return __int_as_float(__float_as_int(p) + (m << 23));
}

// ---------------------------------------------------------------------------
// K0: zero accumulators (graph replays need deterministic reset)
// ---------------------------------------------------------------------------
__global__ void zero_kernel() {
    g_acc[0] = 0.0;
    g_acc[1] = 0.0;
}

// ---------------------------------------------------------------------------
// K1: L2-normalize rows of [emb_i; emb_j] into g_rep. One block per row.
// 128 threads, each owns one float4 (512 floats / 4 / 128 = 1).
// ---------------------------------------------------------------------------
__global__ void normalize_kernel(const float* __restrict__ a,
                                 const float* __restrict__ b) {
    int row = blockIdx.x;
    const float* src = (row < HALF) ? (a + (size_t)row * D)
                                    : (b + (size_t)(row - HALF) * D);
    int tid = threadIdx.x;  // 128

    float4 v = reinterpret_cast<const float4*>(src)[tid];
    float ss = v.x * v.x + v.y * v.y + v.z * v.z + v.w * v.w;

    // warp reduce
    #pragma unroll
    for (int o = 16; o > 0; o >>= 1)
        ss += __shfl_xor_sync(0xFFFFFFFFu, ss, o);

    __shared__ float warp_sums[4];
    int wid = tid >> 5, lane = tid & 31;
    if (lane == 0) warp_sums[wid] = ss;
    __syncthreads();

    float total = warp_sums[0] + warp_sums[1] + warp_sums[2] + warp_sums[3];
    float inv = rsqrtf(fmaxf(total, 1e-24f));  // matches max(norm, 1e-12)

    float4 o4;
    o4.x = v.x * inv; o4.y = v.y * inv; o4.z = v.z * inv; o4.w = v.w * inv;
    reinterpret_cast<float4*>(g_rep + (size_t)row * D)[tid] = o4;
}

// ---------------------------------------------------------------------------
// K2: fused symmetric GEMM + exp + sum over the strict upper triangle.
// Grid 64x64 tiles; tiles with bj < bi exit immediately (symmetry).
// Off-diagonal tiles contribute weight 2; diagonal tiles weight 2 for j>i
// and 0 for j<=i (diagonal itself excluded analytically).
// ---------------------------------------------------------------------------
__global__ __launch_bounds__(NTHREADS, 2)
void gemm_exp_kernel() {
    int bi = blockIdx.y;
    int bj = blockIdx.x;
    if (bj < bi) return;

    __shared__ float As[BK][BM];
    __shared__ float Bs[BK][BN];

    int tid = threadIdx.x;
    const float* Abase = g_rep + (size_t)bi * BM * D;
    const float* Bbase = g_rep + (size_t)bj * BN * D;

    float acc[TM][TN];
    #pragma unroll
    for (int m = 0; m < TM; m++)
        #pragma unroll
        for (int n = 0; n < TN; n++)
            acc[m][n] = 0.0f;

    int ty = tid >> 4;   // 0..15 -> row group
    int tx = tid & 15;   // 0..15 -> col group

    for (int kk = 0; kk < D; kk += BK) {
        // Cooperative load: 128 rows x 16 floats per operand = 512 float4;
        // each of 256 threads moves 2 float4 per operand.
        #pragma unroll
        for (int s = 0; s < 2; s++) {
            int idx = tid + s * NTHREADS;
            int row = idx >> 2;
            int c4  = (idx & 3) << 2;
            float4 a = *reinterpret_cast<const float4*>(Abase + (size_t)row * D + kk + c4);
            float4 b = *reinterpret_cast<const float4*>(Bbase + (size_t)row * D + kk + c4);
            As[c4 + 0][row] = a.x; As[c4 + 1][row] = a.y;
            As[c4 + 2][row] = a.z; As[c4 + 3][row] = a.w;
            Bs[c4 + 0][row] = b.x; Bs[c4 + 1][row] = b.y;
            Bs[c4 + 2][row] = b.z; Bs[c4 + 3][row] = b.w;
        }
        __syncthreads();

        #pragma unroll
        for (int k = 0; k < BK; k++) {
            float ra[TM], rb[TN];
            // contiguous 32B-aligned -> LDS.128 pairs
            *reinterpret_cast<float4*>(&ra[0]) = *reinterpret_cast<const float4*>(&As[k][ty * TM]);
            *reinterpret_cast<float4*>(&ra[4]) = *reinterpret_cast<const float4*>(&As[k][ty * TM + 4]);
            *reinterpret_cast<float4*>(&rb[0]) = *reinterpret_cast<const float4*>(&Bs[k][tx * TN]);
            *reinterpret_cast<float4*>(&rb[4]) = *reinterpret_cast<const float4*>(&Bs[k][tx * TN + 4]);
            #pragma unroll
            for (int m = 0; m < TM; m++)
                #pragma unroll
                for (int n = 0; n < TN; n++)
                    acc[m][n] = fmaf(ra[m], rb[n], acc[m][n]);
        }
        __syncthreads();
    }

    // Epilogue: exp(sim/tau) = exp(2*dot), weighted sum.
    bool diag = (bi == bj);
    float sum = 0.0f;
    #pragma unroll
    for (int m = 0; m < TM; m++) {
        int gi = bi * BM + ty * TM + m;
        #pragma unroll
        for (int n = 0; n < TN; n++) {
            int gj = bj * BN + tx * TN + n;
            float e = fast_exp(2.0f * acc[m][n]);
            float w = diag ? ((gj > gi) ? 2.0f : 0.0f) : 2.0f;
            sum = fmaf(w, e, sum);
        }
    }

    // Block reduction -> one double atomic per tile
    __shared__ float red[NTHREADS];
    red[tid] = sum;
    __syncthreads();
    #pragma unroll
    for (int s = NTHREADS / 2; s >= 32; s >>= 1) {
        if (tid < s) red[tid] += red[tid + s];
        __syncthreads();
    }
    if (tid < 32) {
        float v = red[tid];
        #pragma unroll
        for (int o = 16; o > 0; o >>= 1)
            v += __shfl_xor_sync(0xFFFFFFFFu, v, o);
        if (tid == 0) atomicAdd(&g_acc[0], (double)v);
    }
}

// ---------------------------------------------------------------------------
// K3: nominator — 12288 dot products along offsets {2048, 4096, 6144}.
// One warp per dot; factor 2 covers the mirrored (negative-offset) diagonals.
// ---------------------------------------------------------------------------
__global__ void nominator_kernel() {
    int gw   = (blockIdx.x * blockDim.x + threadIdx.x) >> 5;  // global warp id
    int lane = threadIdx.x & 31;

    int i, k;
    if (gw < 6144)       { k = BPOS;     i = gw;         }
    else if (gw < 10240) { k = 2 * BPOS; i = gw - 6144;  }
    else                 { k = 3 * BPOS; i = gw - 10240; }

    const float* x = g_rep + (size_t)i * D;
    const float* y = g_rep + (size_t)(i + k) * D;

    float s = 0.0f;
    #pragma unroll
    for (int c = 0; c < 4; c++) {
        int base = (lane + c * 32) * 4;
        float4 xv = *reinterpret_cast<const float4*>(x + base);
        float4 yv = *reinterpret_cast<const float4*>(y + base);
        s = fmaf(xv.x, yv.x, s);
        s = fmaf(xv.y, yv.y, s);
        s = fmaf(xv.z, yv.z, s);
        s = fmaf(xv.w, yv.w, s);
    }
    #pragma unroll
    for (int o = 16; o > 0; o >>= 1)
        s += __shfl_xor_sync(0xFFFFFFFFu, s, o);

    if (lane == 0)
        atomicAdd(&g_acc[1], 2.0 * (double)fast_exp(2.0f * s));
}

// ---------------------------------------------------------------------------
// K4: finalize
// ---------------------------------------------------------------------------
__global__ void finalize_kernel(float* __restrict__ out) {
    double nom = g_acc[1];
    double den = g_acc[0] - nom;   // S_offdiag already excludes the diagonal
    out[0] = (float)(-log(nom / den) / (double)NROWS);
}

// ---------------------------------------------------------------------------
// Entry point
// ---------------------------------------------------------------------------
extern "C" void kernel_launch(void* const* d_in, const int* in_sizes, int n_in,
                              void* d_out, int out_size) {
    const float* emb_i = (const float*)d_in[0];
    const float* emb_j = (const float*)d_in[1];
    float* out = (float*)d_out;

    zero_kernel<<<1, 1>>>();
    normalize_kernel<<<NROWS, 128>>>(emb_i, emb_j);
    gemm_exp_kernel<<<dim3(64, 64), NTHREADS>>>();
    nominator_kernel<<<1536, 256>>>();   // 12288 warps
    finalize_kernel<<<1, 1>>>(out);
}

// round 3
// speedup vs baseline: 8.0273x; 8.0273x over previous
#include <cuda_runtime.h>
#include <cuda_bf16.h>
#include <math.h>
#include <cstdint>

// ---------------------------------------------------------------------------
// Problem constants
// ---------------------------------------------------------------------------
#define NROWS 8192       // 4B rows in rep
#define HALF  4096       // rows per input
#define D     512        // embedding dim

// GEMM config: 128x128 CTA tile, K chunked by 64 bf16 (128 B rows), 8 warps
#define TILE   128
#define KC     64
#define NCHUNK (D / KC)          // 8
#define NT     256
#define STAGE_B (TILE * KC * 2)  // 16384 bytes per operand per stage
#define SMEM_DYN (4 * STAGE_B)   // 2 stages x (A + B) = 64 KB

// ---------------------------------------------------------------------------
// Static scratch
// ---------------------------------------------------------------------------
__device__ __align__(16) __nv_bfloat16 g_repb[(size_t)NROWS * D];  // 8 MB
__device__ double g_acc[2];   // [0] = S_offdiag (x2-weighted), [1] = nominator

// ---------------------------------------------------------------------------
// Helpers
// ---------------------------------------------------------------------------
__device__ __forceinline__ uint32_t smem_u32(const void* p) {
    uint32_t a;
    asm("{ .reg .u64 t; cvta.to.shared.u64 t, %1; cvt.u32.u64 %0, t; }"
        : "=r"(a) : "l"(p));
    return a;
}

__device__ __forceinline__ void cp16(uint32_t dst, const void* src) {
    asm volatile("cp.async.cg.shared.global [%0], [%1], 16;"
                 :: "r"(dst), "l"(src));
}
#define CP_COMMIT() asm volatile("cp.async.commit_group;" ::: "memory")
#define CP_WAIT(n)  asm volatile("cp.async.wait_group %0;" :: "n"(n) : "memory")

__device__ __forceinline__ void ldmx4(uint32_t& r0, uint32_t& r1,
                                      uint32_t& r2, uint32_t& r3, uint32_t a) {
    asm volatile("ldmatrix.sync.aligned.m8n8.x4.shared.b16 {%0,%1,%2,%3}, [%4];"
                 : "=r"(r0), "=r"(r1), "=r"(r2), "=r"(r3) : "r"(a));
}

__device__ __forceinline__ void mma16816(float* c, const uint32_t* a,
                                         const uint32_t* b) {
    asm volatile(
        "mma.sync.aligned.m16n8k16.row.col.f32.bf16.bf16.f32 "
        "{%0,%1,%2,%3}, {%4,%5,%6,%7}, {%8,%9}, {%0,%1,%2,%3};"
        : "+f"(c[0]), "+f"(c[1]), "+f"(c[2]), "+f"(c[3])
        : "r"(a[0]), "r"(a[1]), "r"(a[2]), "r"(a[3]), "r"(b[0]), "r"(b[1]));
}

// FMA-only exp for x in ~[-2.5, 2.5] (avoids MUFU pipe). Rel err <= ~4e-6.
__device__ __forceinline__ float fast_exp(float x) {
    float t  = x * 1.44269504088896341f;
    float fn = t + 12582912.0f;
    int   m  = __float_as_int(fn) - 0x4B400000;
    float r  = t - (fn - 12582912.0f);
    float p  = 1.3333558146e-3f;
    p = fmaf(p, r, 9.6181291e-3f);
    p = fmaf(p, r, 5.5504108664e-2f);
    p = fmaf(p, r, 2.4022650696e-1f);
    p = fmaf(p, r, 6.9314718056e-1f);
    p = fmaf(p, r, 1.0f);
    return __int_as_float(__float_as_int(p) + (m << 23));
}

// ---------------------------------------------------------------------------
// K0: zero accumulators (deterministic per graph replay)
// ---------------------------------------------------------------------------
__global__ void zero_kernel() { g_acc[0] = 0.0; g_acc[1] = 0.0; }

// ---------------------------------------------------------------------------
// K1: L2-normalize rows of [emb_i; emb_j] -> bf16 g_repb. One block per row.
// ---------------------------------------------------------------------------
__global__ void normalize_kernel(const float* __restrict__ a,
                                 const float* __restrict__ b) {
    int row = blockIdx.x;
    const float* src = (row < HALF) ? (a + (size_t)row * D)
                                    : (b + (size_t)(row - HALF) * D);
    int tid = threadIdx.x;  // 128

    float4 v = reinterpret_cast<const float4*>(src)[tid];
    float ss = v.x * v.x + v.y * v.y + v.z * v.z + v.w * v.w;

    #pragma unroll
    for (int o = 16; o > 0; o >>= 1)
        ss += __shfl_xor_sync(0xFFFFFFFFu, ss, o);

    __shared__ float ws[4];
    int wid = tid >> 5, lane = tid & 31;
    if (lane == 0) ws[wid] = ss;
    __syncthreads();

    float total = ws[0] + ws[1] + ws[2] + ws[3];
    float inv = rsqrtf(fmaxf(total, 1e-24f));  // == x / max(norm, 1e-12)

    __nv_bfloat162 lo = __floats2bfloat162_rn(v.x * inv, v.y * inv);
    __nv_bfloat162 hi = __floats2bfloat162_rn(v.z * inv, v.w * inv);
    uint2 pk;
    pk.x = *reinterpret_cast<uint32_t*>(&lo);
    pk.y = *reinterpret_cast<uint32_t*>(&hi);
    reinterpret_cast<uint2*>(g_repb + (size_t)row * D)[tid] = pk;
}

// ---------------------------------------------------------------------------
// Stage loader: 128 rows x 128B per operand, 16B chunks, XOR swizzle
// chunk' = chunk ^ (row & 7) keeps both cp.async stores and ldmatrix
// reads conflict-free.
// ---------------------------------------------------------------------------
__device__ __forceinline__ void load_stage(uint32_t sA, uint32_t sB,
                                           const __nv_bfloat16* __restrict__ Ab,
                                           const __nv_bfloat16* __restrict__ Bb,
                                           int kk, int tid) {
    #pragma unroll
    for (int s = 0; s < 4; s++) {
        int idx = tid + s * NT;          // 0..1023
        int row = idx >> 3;              // 0..127
        int ch  = idx & 7;               // 16B chunk in 128B row
        uint32_t dst = (uint32_t)(row * 128 + ((ch ^ (row & 7)) << 4));
        cp16(sA + dst, Ab + (size_t)row * D + kk + ch * 8);
        cp16(sB + dst, Bb + (size_t)row * D + kk + ch * 8);
    }
}

// ---------------------------------------------------------------------------
// K2: mma.sync bf16 GEMM (upper-triangular tiles) fused with exp(2*dot)
// reduction. Nominator diagonals (bj-bi in {16,32,48}, local n==m) are
// accumulated separately — no separate nominator kernel.
// ---------------------------------------------------------------------------
__global__ __launch_bounds__(NT, 2)
void gemm_exp_kernel() {
    int bi = blockIdx.y;
    int bj = blockIdx.x;
    if (bj < bi) return;

    extern __shared__ char sm[];
    uint32_t sbase = smem_u32(sm);

    const int tid    = threadIdx.x;
    const int wid    = tid >> 5;
    const int lane   = tid & 31;
    const int warp_m = wid & 1;      // 2 warps down M (64 rows each)
    const int warp_n = wid >> 1;     // 4 warps across N (32 cols each)

    const __nv_bfloat16* __restrict__ Ab = g_repb + (size_t)bi * TILE * D;
    const __nv_bfloat16* __restrict__ Bb = g_repb + (size_t)bj * TILE * D;

    float acc[4][4][4];   // [mf][nf][frag]
    #pragma unroll
    for (int mf = 0; mf < 4; mf++)
        #pragma unroll
        for (int nf = 0; nf < 4; nf++)
            #pragma unroll
            for (int e = 0; e < 4; e++)
                acc[mf][nf][e] = 0.0f;

    // Per-lane ldmatrix address components (swizzle-aware)
    const int a_row = lane & 15;          // row within 16-row frag
    const int a_hi  = lane >> 4;          // 0/1: k-halves
    const int a_sw  = a_row & 7;
    const int b_n   = ((lane >> 4) << 3) + (lane & 7);  // n within 16
    const int b_hi  = (lane >> 3) & 1;
    const int b_sw  = b_n & 7;

    // Prologue: fill both stages
    load_stage(sbase,         sbase + STAGE_B,     Ab, Bb, 0,  tid);
    CP_COMMIT();
    load_stage(sbase + 2 * STAGE_B, sbase + 3 * STAGE_B, Ab, Bb, KC, tid);
    CP_COMMIT();
    CP_WAIT(1);
    __syncthreads();

    for (int j = 0; j < NCHUNK; j++) {
        uint32_t sA = sbase + (uint32_t)(j & 1) * 2 * STAGE_B;
        uint32_t sB = sA + STAGE_B;

        #pragma unroll
        for (int ks = 0; ks < 4; ks++) {
            uint32_t afr[4][4];
            #pragma unroll
            for (int mf = 0; mf < 4; mf++) {
                int grow = warp_m * 64 + mf * 16 + a_row;
                uint32_t ca = (uint32_t)((2 * ks + a_hi) ^ a_sw);
                ldmx4(afr[mf][0], afr[mf][1], afr[mf][2], afr[mf][3],
                      sA + grow * 128 + ca * 16);
            }
            uint32_t bfr[4][2];
            #pragma unroll
            for (int np = 0; np < 2; np++) {
                int gn = warp_n * 32 + np * 16 + b_n;
                uint32_t cb = (uint32_t)((2 * ks + b_hi) ^ b_sw);
                uint32_t r0, r1, r2, r3;
                ldmx4(r0, r1, r2, r3, sB + gn * 128 + cb * 16);
                bfr[2 * np][0] = r0; bfr[2 * np][1] = r1;
                bfr[2 * np + 1][0] = r2; bfr[2 * np + 1][1] = r3;
            }
            #pragma unroll
            for (int mf = 0; mf < 4; mf++)
                #pragma unroll
                for (int nf = 0; nf < 4; nf++)
                    mma16816(acc[mf][nf], afr[mf], bfr[nf]);
        }

        __syncthreads();   // all warps done reading this stage
        if (j + 2 < NCHUNK) {
            load_stage(sA, sB, Ab, Bb, (j + 2) * KC, tid);
            CP_COMMIT();
            CP_WAIT(1);
            __syncthreads();
        } else if (j + 1 < NCHUNK) {
            CP_WAIT(0);
            __syncthreads();
        }
    }

    // Epilogue: exp(2*dot) + masked sums directly from register fragments.
    const bool diag = (bi == bj);
    const int  dbj  = bj - bi;
    const bool nomt = (dbj == 16) | (dbj == 32) | (dbj == 48);
    const int  grp  = lane >> 2;          // d-frag row within 8
    const int  tig  = lane & 3;           // d-frag col pair

    float sum = 0.0f, nom = 0.0f;
    #pragma unroll
    for (int mf = 0; mf < 4; mf++) {
        #pragma unroll
        for (int nf = 0; nf < 4; nf++) {
            int m0 = warp_m * 64 + mf * 16 + grp;
            int n0 = warp_n * 32 + nf * 8 + tig * 2;
            #pragma unroll
            for (int e = 0; e < 4; e++) {
                int mm = m0 + (e >> 1) * 8;
                int nn = n0 + (e & 1);
                float ex = fast_exp(2.0f * acc[mf][nf][e]);
                if (!diag || nn > mm) sum += ex;
                if (nomt & (nn == mm)) nom += ex;
            }
        }
    }

    // Block reduction -> one double atomic per tile (reuse stage smem)
    __syncthreads();
    float2* red = reinterpret_cast<float2*>(sm);
    red[tid] = make_float2(sum, nom);
    __syncthreads();
    #pragma unroll
    for (int s2 = NT / 2; s2 >= 32; s2 >>= 1) {
        if (tid < s2) {
            float2 o = red[tid + s2];
            red[tid].x += o.x;
            red[tid].y += o.y;
        }
        __syncthreads();
    }
    if (tid < 32) {
        float2 v2 = red[tid];
        #pragma unroll
        for (int o = 16; o > 0; o >>= 1) {
            v2.x += __shfl_xor_sync(0xFFFFFFFFu, v2.x, o);
            v2.y += __shfl_xor_sync(0xFFFFFFFFu, v2.y, o);
        }
        if (tid == 0) {
            atomicAdd(&g_acc[0], 2.0 * (double)v2.x);   // mirror lower triangle
            if (v2.y != 0.0f) atomicAdd(&g_acc[1], 2.0 * (double)v2.y);
        }
    }
}

// ---------------------------------------------------------------------------
// K3: finalize
// ---------------------------------------------------------------------------
__global__ void finalize_kernel(float* __restrict__ out) {
    double nom = g_acc[1];
    double den = g_acc[0] - nom;    // full off-diag sum minus nominator
    out[0] = (float)(-log(nom / den) / (double)NROWS);
}

// ---------------------------------------------------------------------------
// Entry point
// ---------------------------------------------------------------------------
extern "C" void kernel_launch(void* const* d_in, const int* in_sizes, int n_in,
                              void* d_out, int out_size) {
    const float* emb_i = (const float*)d_in[0];
    const float* emb_j = (const float*)d_in[1];
    float* out = (float*)d_out;

    cudaFuncSetAttribute(gemm_exp_kernel,
                         cudaFuncAttributeMaxDynamicSharedMemorySize, SMEM_DYN);

    zero_kernel<<<1, 1>>>();
    normalize_kernel<<<NROWS, 128>>>(emb_i, emb_j);
    gemm_exp_kernel<<<dim3(64, 64), NT, SMEM_DYN>>>();
    finalize_kernel<<<1, 1>>>(out);
}